// round 2
// baseline (speedup 1.0000x reference)
#include <cuda_runtime.h>
#include <cuda_bf16.h>
#include <math.h>

#define N_USERS 100000
#define N_ITEMS 50000
#define N_TOT   150000
#define IN_DIM  768
#define BR      64
#define NE      2097152
#define BATCHB  4096
#define NCAND   128
#define NNEG    16
#define DIM     128
#define INV_SQRT2 0.70710678118f
#define NB_SCAN 147   /* ceil(150000/1024) */

// ---------------- scratch (device globals; no runtime allocation) ----------------
// NOTE: these are ONLY referenced from device code. Referencing them in host code
// yields the host shadow symbol, which on GB300 (ATS) silently "works" and reads
// host memory — that was the Round-1 bug.
__device__ float g_ego_a[(size_t)N_TOT * BR];
__device__ float g_ego_b[(size_t)N_TOT * BR];
__device__ float g_acc  [(size_t)N_TOT * BR];
__device__ float g_i_all[(size_t)N_ITEMS * DIM];
__device__ float g_batch_u[(size_t)BATCHB * DIM];
__device__ int   g_row_ptr[N_TOT + 1];
__device__ int   g_row_cnt[N_TOT];
__device__ int   g_row_fill[N_TOT];
__device__ int   g_col_sorted[NE];
__device__ float g_val_sorted[NE];
__device__ int   g_bsum[256];
__device__ float g_loss;

// ---------------- init / zero ----------------
__global__ void k_zero() {
    int i = blockIdx.x * blockDim.x + threadIdx.x;
    if (i < N_TOT) { g_row_cnt[i] = 0; g_row_fill[i] = 0; }
    if (i == 0) g_loss = 0.0f;
}

__global__ void k_init_ego(const float* __restrict__ uw, const float* __restrict__ iw) {
    int idx = blockIdx.x * blockDim.x + threadIdx.x;
    if (idx >= N_TOT * BR) return;
    int row = idx >> 6, c = idx & 63;
    float v = (row < N_USERS) ? uw[row * BR + c] : iw[(row - N_USERS) * BR + c];
    g_ego_a[idx] = v;
    g_acc[idx]   = v;
}

// ---------------- CSR build ----------------
__global__ void k_hist(const int* __restrict__ rows) {
    int i = blockIdx.x * blockDim.x + threadIdx.x;
    if (i < NE) atomicAdd(&g_row_cnt[rows[i]], 1);
}

__global__ void k_scan1() {
    __shared__ int red[256];
    int b = blockIdx.x, t = threadIdx.x;
    int base = b * 1024 + t * 4;
    int s = 0;
    #pragma unroll
    for (int q = 0; q < 4; q++) { int i = base + q; if (i < N_TOT) s += g_row_cnt[i]; }
    red[t] = s; __syncthreads();
    for (int off = 128; off > 0; off >>= 1) {
        if (t < off) red[t] += red[t + off];
        __syncthreads();
    }
    if (t == 0) g_bsum[b] = red[0];
}

__global__ void k_scan2() {
    if (threadIdx.x == 0 && blockIdx.x == 0) {
        int run = 0;
        for (int i = 0; i < NB_SCAN; i++) { int t = g_bsum[i]; g_bsum[i] = run; run += t; }
    }
}

__global__ void k_scan3() {
    __shared__ int tsum[256];
    int b = blockIdx.x, t = threadIdx.x;
    int base = b * 1024 + t * 4;
    int c0 = 0, c1 = 0, c2 = 0, c3 = 0;
    if (base + 0 < N_TOT) c0 = g_row_cnt[base + 0];
    if (base + 1 < N_TOT) c1 = g_row_cnt[base + 1];
    if (base + 2 < N_TOT) c2 = g_row_cnt[base + 2];
    if (base + 3 < N_TOT) c3 = g_row_cnt[base + 3];
    int p1 = c0, p2 = c0 + c1, p3 = c0 + c1 + c2, s = p3 + c3;
    tsum[t] = s; __syncthreads();
    for (int off = 1; off < 256; off <<= 1) {
        int v = (t >= off) ? tsum[t - off] : 0;
        __syncthreads();
        tsum[t] += v;
        __syncthreads();
    }
    int excl = tsum[t] - s + g_bsum[b];
    if (base + 0 < N_TOT) g_row_ptr[base + 0] = excl;
    if (base + 1 < N_TOT) g_row_ptr[base + 1] = excl + p1;
    if (base + 2 < N_TOT) g_row_ptr[base + 2] = excl + p2;
    if (base + 3 < N_TOT) g_row_ptr[base + 3] = excl + p3;
    if (b == 0 && t == 0) g_row_ptr[N_TOT] = NE;
}

__global__ void k_scatter(const int* __restrict__ rows, const int* __restrict__ cols,
                          const float* __restrict__ vals) {
    int i = blockIdx.x * blockDim.x + threadIdx.x;
    if (i >= NE) return;
    int r = rows[i];
    int ofs = atomicAdd(&g_row_fill[r], 1);
    int d = g_row_ptr[r] + ofs;
    g_col_sorted[d] = cols[i];
    g_val_sorted[d] = vals[i];
}

// ---------------- SpMM: warp per destination row; buffer selected in DEVICE code ----------------
__global__ void k_spmm(int phase) {
    const float* __restrict__ in = (phase & 1) ? g_ego_b : g_ego_a;
    float* __restrict__ outp     = (phase & 1) ? g_ego_a : g_ego_b;
    int w = (blockIdx.x * blockDim.x + threadIdx.x) >> 5;
    int lane = threadIdx.x & 31;
    if (w >= N_TOT) return;
    int s = g_row_ptr[w], e = g_row_ptr[w + 1];
    float a0 = 0.0f, a1 = 0.0f;
    for (int base = s; base < e; base += 32) {
        int idx = base + lane;
        int c = 0; float v = 0.0f;
        if (idx < e) { c = g_col_sorted[idx]; v = g_val_sorted[idx]; }
        int cnt = min(32, e - base);
        for (int j = 0; j < cnt; j++) {
            int cc = __shfl_sync(0xffffffffu, c, j);
            float vv = __shfl_sync(0xffffffffu, v, j);
            const float* p = in + (size_t)cc * BR;
            a0 = fmaf(vv, __ldg(p + lane), a0);
            a1 = fmaf(vv, __ldg(p + lane + 32), a1);
        }
    }
    size_t o = (size_t)w * BR;
    outp[o + lane] = a0;
    outp[o + lane + 32] = a1;
    g_acc[o + lane] += a0;
    g_acc[o + lane + 32] += a1;
}

// ---------------- collab halves: normalize(acc row) * (1/sqrt2) ----------------
__global__ void k_collab_items() {
    int w = (blockIdx.x * blockDim.x + threadIdx.x) >> 5;
    int lane = threadIdx.x & 31;
    if (w >= N_ITEMS) return;
    size_t o = (size_t)(N_USERS + w) * BR;
    float v0 = g_acc[o + lane], v1 = g_acc[o + lane + 32];
    float ss = v0 * v0 + v1 * v1;
    #pragma unroll
    for (int off = 16; off > 0; off >>= 1) ss += __shfl_xor_sync(0xffffffffu, ss, off);
    float sc = INV_SQRT2 / fmaxf(sqrtf(ss), 1e-12f);
    g_i_all[(size_t)w * DIM + lane] = v0 * sc;
    g_i_all[(size_t)w * DIM + lane + 32] = v1 * sc;
}

__global__ void k_collab_users(const int* __restrict__ uids) {
    int w = (blockIdx.x * blockDim.x + threadIdx.x) >> 5;
    int lane = threadIdx.x & 31;
    if (w >= BATCHB) return;
    int u = uids[w];
    size_t o = (size_t)u * BR;
    float v0 = g_acc[o + lane], v1 = g_acc[o + lane + 32];
    float ss = v0 * v0 + v1 * v1;
    #pragma unroll
    for (int off = 16; off > 0; off >>= 1) ss += __shfl_xor_sync(0xffffffffu, ss, off);
    float sc = INV_SQRT2 / fmaxf(sqrtf(ss), 1e-12f);
    g_batch_u[(size_t)w * DIM + lane] = v0 * sc;
    g_batch_u[(size_t)w * DIM + lane + 32] = v1 * sc;
}

// ---------------- semantic GEMM: out[row][64..127] = normalize(A[row]@W + b)/sqrt2 ----------------
// BM=128, BN=64, BK=16, 256 threads, thread tile 8x4. Row-normalize in epilogue.
// Output global selected in DEVICE code via template flag.
template<bool GATHER>
__global__ void k_sem_gemm(const float* __restrict__ A, const float* __restrict__ W,
                           const float* __restrict__ bias, const int* __restrict__ gidx,
                           int M) {
    float* __restrict__ outp = GATHER ? g_batch_u : g_i_all;
    __shared__ float As[16][128];
    __shared__ float Bs[16][64];
    __shared__ float Cs[128][68];  // +4 pad: kills bank conflicts, keeps float4 alignment

    int t = threadIdx.x;
    int rowbase = blockIdx.x * 128;
    int tx = t & 15, ty = t >> 4;

    float acc[8][4];
    #pragma unroll
    for (int i = 0; i < 8; i++)
        #pragma unroll
        for (int j = 0; j < 4; j++) acc[i][j] = 0.0f;

    int aRow0 = t >> 2;
    int aK4 = (t & 3) * 4;
    int gr0 = rowbase + aRow0;
    int gr1 = rowbase + aRow0 + 64;
    bool val0 = gr0 < M, val1 = gr1 < M;
    int srow0 = val0 ? (GATHER ? gidx[gr0] : gr0) : 0;
    int srow1 = val1 ? (GATHER ? gidx[gr1] : gr1) : 0;
    const float* rp0 = A + (size_t)srow0 * IN_DIM;
    const float* rp1 = A + (size_t)srow1 * IN_DIM;

    int bK = t >> 4;
    int bC = (t & 15) * 4;

    for (int k0 = 0; k0 < IN_DIM; k0 += 16) {
        float4 a0 = val0 ? *(const float4*)(rp0 + k0 + aK4) : make_float4(0, 0, 0, 0);
        float4 a1 = val1 ? *(const float4*)(rp1 + k0 + aK4) : make_float4(0, 0, 0, 0);
        float4 bv = *(const float4*)(W + (size_t)(k0 + bK) * BR + bC);
        __syncthreads();
        As[aK4 + 0][aRow0] = a0.x; As[aK4 + 1][aRow0] = a0.y;
        As[aK4 + 2][aRow0] = a0.z; As[aK4 + 3][aRow0] = a0.w;
        As[aK4 + 0][aRow0 + 64] = a1.x; As[aK4 + 1][aRow0 + 64] = a1.y;
        As[aK4 + 2][aRow0 + 64] = a1.z; As[aK4 + 3][aRow0 + 64] = a1.w;
        *(float4*)&Bs[bK][bC] = bv;
        __syncthreads();
        #pragma unroll
        for (int kk = 0; kk < 16; kk++) {
            float4 aA = *(const float4*)&As[kk][ty * 8];
            float4 aB = *(const float4*)&As[kk][ty * 8 + 4];
            float4 bb = *(const float4*)&Bs[kk][tx * 4];
            float ar[8] = {aA.x, aA.y, aA.z, aA.w, aB.x, aB.y, aB.z, aB.w};
            float bc[4] = {bb.x, bb.y, bb.z, bb.w};
            #pragma unroll
            for (int i = 0; i < 8; i++)
                #pragma unroll
                for (int j = 0; j < 4; j++) acc[i][j] = fmaf(ar[i], bc[j], acc[i][j]);
        }
    }

    __syncthreads();
    #pragma unroll
    for (int i = 0; i < 8; i++)
        #pragma unroll
        for (int j = 0; j < 4; j++)
            Cs[ty * 8 + i][tx * 4 + j] = acc[i][j] + bias[tx * 4 + j];
    __syncthreads();

    int rr = t >> 1, h = t & 1;
    const float* cb = &Cs[rr][h * 32];
    float ss = 0.0f;
    #pragma unroll
    for (int j = 0; j < 32; j++) ss += cb[j] * cb[j];
    ss += __shfl_xor_sync(0xffffffffu, ss, 1);
    float scl = INV_SQRT2 / fmaxf(sqrtf(ss), 1e-12f);
    int gr = rowbase + rr;
    if (gr < M) {
        float* op = outp + (size_t)gr * DIM + BR + h * 32;
        #pragma unroll
        for (int j = 0; j < 32; j += 4) {
            float4 v = *(const float4*)(cb + j);
            v.x *= scl; v.y *= scl; v.z *= scl; v.w *= scl;
            *(float4*)(op + j) = v;
        }
    }
}

// ---------------- scoring: block per batch row ----------------
__global__ void k_score(const int* __restrict__ pos_iids, const int* __restrict__ cand_ids) {
    __shared__ __align__(16) float su[128];
    __shared__ float sc[128];
    int b = blockIdx.x, t = threadIdx.x;
    su[t] = g_batch_u[(size_t)b * DIM + t];
    __syncthreads();
    int pos = pos_iids[b];
    int id = cand_ids[(size_t)b * NCAND + t];
    if (id == pos) id = (id + 1) % N_ITEMS;
    const float4* ip = (const float4*)(g_i_all + (size_t)id * DIM);
    const float4* us = (const float4*)su;
    float a = 0.0f;
    #pragma unroll
    for (int j = 0; j < 32; j++) {
        float4 iv = __ldg(ip + j);
        float4 uv = us[j];
        a += iv.x * uv.x + iv.y * uv.y + iv.z * uv.z + iv.w * uv.w;
    }
    sc[t] = a;
    __syncthreads();

    if (t < 32) {
        const float* pp = g_i_all + (size_t)pos * DIM;
        float p = pp[t] * su[t] + pp[t + 32] * su[t + 32] +
                  pp[t + 64] * su[t + 64] + pp[t + 96] * su[t + 96];
        #pragma unroll
        for (int off = 16; off > 0; off >>= 1) p += __shfl_xor_sync(0xffffffffu, p, off);

        float v0 = sc[t * 4], v1 = sc[t * 4 + 1], v2 = sc[t * 4 + 2], v3 = sc[t * 4 + 3];
        float Lmax = 0.0f, S = 0.0f;
        for (int it = 0; it < NNEG; it++) {
            float best = v0; int bq = 0;
            if (v1 > best) { best = v1; bq = 1; }
            if (v2 > best) { best = v2; bq = 2; }
            if (v3 > best) { best = v3; bq = 3; }
            float wb = best;
            #pragma unroll
            for (int off = 16; off > 0; off >>= 1) wb = fmaxf(wb, __shfl_xor_sync(0xffffffffu, wb, off));
            unsigned m = __ballot_sync(0xffffffffu, best == wb);
            int owner = __ffs(m) - 1;
            if (t == owner) {
                if (bq == 0) v0 = -3.0e38f;
                else if (bq == 1) v1 = -3.0e38f;
                else if (bq == 2) v2 = -3.0e38f;
                else v3 = -3.0e38f;
            }
            float l = wb * 10.0f;  // /TEMP
            if (it == 0) { Lmax = l; S = 1.0f; }
            else S += __expf(l - Lmax);
        }
        float lp = p * 10.0f;
        if (lp > Lmax) { S = S * __expf(Lmax - lp) + 1.0f; Lmax = lp; }
        else S += __expf(lp - Lmax);
        float lossb = Lmax + logf(S) - lp;
        if (t == 0) atomicAdd(&g_loss, lossb);
    }
}

__global__ void k_final(float* out) {
    out[0] = g_loss * (1.0f / (float)BATCHB);
}

// ---------------- launch ----------------
extern "C" void kernel_launch(void* const* d_in, const int* in_sizes, int n_in,
                              void* d_out, int out_size) {
    const float* raw_item_embs = (const float*)d_in[0];
    const float* user_sem_base = (const float*)d_in[1];
    const float* sem_w         = (const float*)d_in[2];
    const float* sem_b         = (const float*)d_in[3];
    const float* collab_user_w = (const float*)d_in[4];
    const float* collab_item_w = (const float*)d_in[5];
    const float* adj_vals      = (const float*)d_in[6];
    const int*   adj_rows      = (const int*)d_in[7];
    const int*   adj_cols      = (const int*)d_in[8];
    const int*   uids          = (const int*)d_in[9];
    const int*   pos_iids      = (const int*)d_in[10];
    const int*   cand_ids      = (const int*)d_in[11];
    float* out = (float*)d_out;

    k_zero<<<(N_TOT + 255) / 256, 256>>>();
    k_init_ego<<<(N_TOT * BR + 255) / 256, 256>>>(collab_user_w, collab_item_w);

    // CSR build
    k_hist<<<NE / 256, 256>>>(adj_rows);
    k_scan1<<<NB_SCAN, 256>>>();
    k_scan2<<<1, 32>>>();
    k_scan3<<<NB_SCAN, 256>>>();
    k_scatter<<<NE / 256, 256>>>(adj_rows, adj_cols, adj_vals);

    // 3 GCN layers (ping-pong selected device-side), acc accumulated in-kernel
    int spmm_blocks = (N_TOT * 32 + 255) / 256;
    k_spmm<<<spmm_blocks, 256>>>(0);   // a -> b
    k_spmm<<<spmm_blocks, 256>>>(1);   // b -> a
    k_spmm<<<spmm_blocks, 256>>>(0);   // a -> b

    // semantic halves (output global chosen in device code)
    k_sem_gemm<false><<<(N_ITEMS + 127) / 128, 256>>>(raw_item_embs, sem_w, sem_b, nullptr, N_ITEMS);
    k_sem_gemm<true><<<BATCHB / 128, 256>>>(user_sem_base, sem_w, sem_b, uids, BATCHB);

    // collaborative halves
    k_collab_items<<<(N_ITEMS * 32 + 255) / 256, 256>>>();
    k_collab_users<<<(BATCHB * 32 + 255) / 256, 256>>>(uids);

    // scoring + loss
    k_score<<<BATCHB, 128>>>(pos_iids, cand_ids);
    k_final<<<1, 1>>>(out);
}